// round 14
// baseline (speedup 1.0000x reference)
#include <cuda_runtime.h>
#include <cuda_fp16.h>
#include <cstdint>

#define Nn 8
#define Cc 128
#define Ll 1024
#define Kk 100
#define EPSf 1e-8f

// Normalized fp16 rows, [N, L, C] (256B per row).
__device__ __half g_zh[Nn * Ll * Cc];
__device__ __half g_ch[Nn * Ll * Cc];

// Fused transpose + norm + normalize + fp16 convert.
// 16-t tiles -> 1024 blocks x 256 threads (4x the blocks of the 32-t version).
__global__ void __launch_bounds__(256) prep_k(const float* __restrict__ zsrc,
                                              const float* __restrict__ csrc) {
    __shared__ float tile[16][129];
    __shared__ float sp[16][16];
    __shared__ float srn[16];

    int zz = blockIdx.y;
    bool is_c = zz >= Nn;
    int n = is_c ? zz - Nn : zz;
    int ld      = is_c ? (Ll + 1) : Ll;
    int col_off = is_c ? 1 : 0;
    int t0 = blockIdx.x * 16;
    const float* s = (is_c ? csrc : zsrc) + (size_t)n * Cc * ld + col_off + t0;
    __half* d = (is_c ? g_ch : g_zh) + ((size_t)n * Ll + t0) * Cc;

    int tid = threadIdx.x;
    int tx  = tid & 15;    // t within tile
    int ty  = tid >> 4;    // 0..15 channel group

    // Load 8 channels for t=tx (coalesced 64B segments over t).
    float acc = 0.f;
#pragma unroll
    for (int i = 0; i < 8; i++) {
        int ch = i * 16 + ty;
        float v = s[(size_t)ch * ld + tx];
        tile[tx][ch] = v;
        acc += v * v;
    }
    sp[ty][tx] = acc;
    __syncthreads();

    if (tid < 16) {
        float sum = 0.f;
#pragma unroll
        for (int y = 0; y < 16; y++) sum += sp[y][tid];
        srn[tid] = 1.0f / fmaxf(sqrtf(sum), EPSf);
    }
    __syncthreads();

    // Write: 16 rows x 16 uint4 = 256 uint4; one per thread, coalesced.
    {
        int t = tid >> 4;
        int k = tid & 15;
        float rn = srn[t];
        __half2 h[4];
#pragma unroll
        for (int q = 0; q < 4; q++) {
            float a = tile[t][k * 8 + 2 * q]     * rn;
            float b = tile[t][k * 8 + 2 * q + 1] * rn;
            h[q] = __floats2half2_rn(a, b);
        }
        ((uint4*)(d + (size_t)t * Cc))[k] = *(const uint4*)h;
    }
}

// Warp-per-row, 8 warps/block. Depth-2 z buffer, smem-staged indices, HFMA2.
// Block->row remap: n = bid & 7, so blocks co-resident on one SM (bids
// congruent mod 148, 148 % 8 == 4) touch only 2 of the 8 z pools -> smaller
// L1 working set on the gathers.
__global__ void __launch_bounds__(256) main_k(const int* __restrict__ neg_inds,
                                              float* __restrict__ out) {
    __shared__ int sidx[8][108];

    int warp = threadIdx.x >> 5;
    int bx   = blockIdx.x;                 // 0..1023
    int n    = bx & 7;
    int t    = ((bx >> 3) << 3) + warp;    // 0..1023
    int r    = (n << 10) + t;
    int lane = threadIdx.x & 31;
    int g    = lane >> 3;                  // dot slot within pass
    int p    = lane & 7;                   // lane within dot

    // Stage indices: slot 0 = t (positive), 1..100 = negatives, 101..107 = t.
    const int* ni = neg_inds + (size_t)r * Kk;
    int* si = sidx[warp];
#pragma unroll
    for (int i = 0; i < 4; i++) {
        int jj = lane + 32 * i;            // 0..127
        if (jj < 108) si[jj] = (jj >= 1 && jj <= Kk) ? ni[jj - 1] : t;
    }
    __syncwarp();

    // c chunk: 16 channels for this lane (slots p and 8+p), kept as half2.
    const uint4* crow = (const uint4*)(g_ch + (size_t)r * Cc);
    uint4 ca = crow[p], cb = crow[8 + p];
    __half2 ch2[8];
    {
        const __half2* h = (const __half2*)&ca;
        ch2[0] = h[0]; ch2[1] = h[1]; ch2[2] = h[2]; ch2[3] = h[3];
        h = (const __half2*)&cb;
        ch2[4] = h[0]; ch2[5] = h[1]; ch2[6] = h[2]; ch2[7] = h[3];
    }

    const uint4* zbase = (const uint4*)(g_zh + ((size_t)n << 10) * Cc);
    float*       orow  = out + (size_t)r * (Kk + 1);

    // Prologue: z for pass 0; index register for pass 1's prefetch.
    int ia = si[g];
    uint4 z0a = zbase[(size_t)ia * 16 + p];
    uint4 z0b = zbase[(size_t)ia * 16 + 8 + p];
    int inext = si[4 + g];

#pragma unroll
    for (int pass = 0; pass < 26; pass++) {
        int j = pass * 4 + g;

        // Prefetch z for pass+1 (index already resident); LDS index for pass+2.
        uint4 ya, yb;
        if (pass < 25) {
            ya = zbase[(size_t)inext * 16 + p];
            yb = zbase[(size_t)inext * 16 + 8 + p];
        }
        if (pass < 24) inext = si[j + 8];

        // 16 products via 8 HFMA2 across two independent accumulators.
        __half2 acc0 = __floats2half2_rn(0.f, 0.f);
        __half2 acc1 = __floats2half2_rn(0.f, 0.f);
        {
            const __half2* zh = (const __half2*)&z0a;
            acc0 = __hfma2(ch2[0], zh[0], acc0);
            acc1 = __hfma2(ch2[1], zh[1], acc1);
            acc0 = __hfma2(ch2[2], zh[2], acc0);
            acc1 = __hfma2(ch2[3], zh[3], acc1);
            zh = (const __half2*)&z0b;
            acc0 = __hfma2(ch2[4], zh[0], acc0);
            acc1 = __hfma2(ch2[5], zh[1], acc1);
            acc0 = __hfma2(ch2[6], zh[2], acc0);
            acc1 = __hfma2(ch2[7], zh[3], acc1);
        }
        float2 f0 = __half22float2(acc0);
        float2 f1 = __half22float2(acc1);
        float a = (f0.x + f0.y) + (f1.x + f1.y);

        a += __shfl_xor_sync(0xffffffffu, a, 1);
        a += __shfl_xor_sync(0xffffffffu, a, 2);
        a += __shfl_xor_sync(0xffffffffu, a, 4);

        if (p == 0 && j <= Kk)
            orow[j] = a * 2.0f;   // norms folded in; / TEMP = *2

        z0a = ya; z0b = yb;
    }
}

extern "C" void kernel_launch(void* const* d_in, const int* in_sizes, int n_in,
                              void* d_out, int out_size) {
    const float* z  = (const float*)d_in[0];  // [N, C, L]
    const float* c  = (const float*)d_in[1];  // [N, C, L+1]
    const int*   ni = (const int*)d_in[2];    // [N, L, K]
    float* out = (float*)d_out;               // [N*L, K+1]

    dim3 pg(Ll / 16, 2 * Nn);
    prep_k<<<pg, 256>>>(z, c);

    main_k<<<Nn * Ll / 8, 256>>>(ni, out);
}

// round 15
// speedup vs baseline: 1.0977x; 1.0977x over previous
#include <cuda_runtime.h>
#include <cuda_fp16.h>
#include <cstdint>

#define Nn 8
#define Cc 128
#define Ll 1024
#define Kk 100
#define EPSf 1e-8f

// Normalized fp16 rows, [N, L, C] (256B per row).
// c rows are scaled by 2/norm (INV_TEMP folded in); z rows by 1/norm.
__device__ __half g_zh[Nn * Ll * Cc];
__device__ __half g_ch[Nn * Ll * Cc];

// Fused: transpose + norm + normalize (+temp fold for c) + fp16 convert.
// 512 threads per 32t x 128ch tile; full 128B load segments over t.
__global__ void __launch_bounds__(512) prep_k(const float* __restrict__ zsrc,
                                              const float* __restrict__ csrc) {
    __shared__ float tile[32][129];
    __shared__ float sp[16][32];
    __shared__ float srn[32];

    int zz = blockIdx.y;
    bool is_c = zz >= Nn;
    int n = is_c ? zz - Nn : zz;
    int ld      = is_c ? (Ll + 1) : Ll;
    int col_off = is_c ? 1 : 0;
    int t0 = blockIdx.x * 32;
    const float* s = (is_c ? csrc : zsrc) + (size_t)n * Cc * ld + col_off + t0;
    __half* d = (is_c ? g_ch : g_zh) + ((size_t)n * Ll + t0) * Cc;
    float nscale = is_c ? 2.0f : 1.0f;     // fold 1/TEMP into c

    int tid = threadIdx.x;
    int tx  = tid & 31;    // t within tile
    int ty  = tid >> 5;    // 0..15

    float acc = 0.f;
#pragma unroll
    for (int i = 0; i < 8; i++) {
        int ch = i * 16 + ty;
        float v = s[(size_t)ch * ld + tx];
        tile[tx][ch] = v;
        acc += v * v;
    }
    sp[ty][tx] = acc;
    __syncthreads();

    if (tid < 32) {
        float sum = 0.f;
#pragma unroll
        for (int y = 0; y < 16; y++) sum += sp[y][tid];
        srn[tid] = nscale / fmaxf(sqrtf(sum), EPSf);
    }
    __syncthreads();

    // Write: 32 rows x 16 uint4 = 512 uint4; one per thread, coalesced.
    {
        int t = tid >> 4;
        int k = tid & 15;
        float rn = srn[t];
        __half2 h[4];
#pragma unroll
        for (int q = 0; q < 4; q++) {
            float a = tile[t][k * 8 + 2 * q]     * rn;
            float b = tile[t][k * 8 + 2 * q + 1] * rn;
            h[q] = __floats2half2_rn(a, b);
        }
        ((uint4*)(d + (size_t)t * Cc))[k] = *(const uint4*)h;
    }
}

// Warp-per-row, 8 warps/block (verified best config: depth-2 z buffer,
// smem-staged indices, HFMA2 dual accumulators). 8 lanes per dot; lane p owns
// uint4 slots p and 8+p (one contiguous 128B line per 8-lane group per LDG).
__global__ void __launch_bounds__(256) main_k(const int* __restrict__ neg_inds,
                                              float* __restrict__ out) {
    __shared__ int sidx[8][108];

    int warp = threadIdx.x >> 5;
    int r    = (blockIdx.x << 3) + warp;   // 0..N*L-1
    int n    = r >> 10;
    int t    = r & (Ll - 1);
    int lane = threadIdx.x & 31;
    int g    = lane >> 3;                  // dot slot within pass
    int p    = lane & 7;                   // lane within dot

    // Stage indices: slot 0 = t (positive), 1..100 = negatives, 101..107 = t.
    const int* ni = neg_inds + (size_t)r * Kk;
    int* si = sidx[warp];
#pragma unroll
    for (int i = 0; i < 4; i++) {
        int jj = lane + 32 * i;            // 0..127
        if (jj < 108) si[jj] = (jj >= 1 && jj <= Kk) ? ni[jj - 1] : t;
    }
    __syncwarp();

    // c chunk: 16 channels for this lane (slots p and 8+p), kept as half2.
    const uint4* crow = (const uint4*)(g_ch + (size_t)r * Cc);
    uint4 ca = crow[p], cb = crow[8 + p];
    __half2 ch2[8];
    {
        const __half2* h = (const __half2*)&ca;
        ch2[0] = h[0]; ch2[1] = h[1]; ch2[2] = h[2]; ch2[3] = h[3];
        h = (const __half2*)&cb;
        ch2[4] = h[0]; ch2[5] = h[1]; ch2[6] = h[2]; ch2[7] = h[3];
    }

    const uint4* zbase = (const uint4*)(g_zh + ((size_t)n << 10) * Cc);
    float*       orow  = out + (size_t)r * (Kk + 1);

    // Prologue: z for pass 0; index register for pass 1's prefetch.
    int ia = si[g];
    uint4 z0a = zbase[(size_t)ia * 16 + p];
    uint4 z0b = zbase[(size_t)ia * 16 + 8 + p];
    int inext = si[4 + g];

#pragma unroll
    for (int pass = 0; pass < 26; pass++) {
        int j = pass * 4 + g;

        // Prefetch z for pass+1 (index already resident); LDS index for pass+2.
        uint4 ya, yb;
        if (pass < 25) {
            ya = zbase[(size_t)inext * 16 + p];
            yb = zbase[(size_t)inext * 16 + 8 + p];
        }
        if (pass < 24) inext = si[j + 8];

        // 16 products via 8 HFMA2 across two independent accumulators.
        __half2 acc0 = __floats2half2_rn(0.f, 0.f);
        __half2 acc1 = __floats2half2_rn(0.f, 0.f);
        {
            const __half2* zh = (const __half2*)&z0a;
            acc0 = __hfma2(ch2[0], zh[0], acc0);
            acc1 = __hfma2(ch2[1], zh[1], acc1);
            acc0 = __hfma2(ch2[2], zh[2], acc0);
            acc1 = __hfma2(ch2[3], zh[3], acc1);
            zh = (const __half2*)&z0b;
            acc0 = __hfma2(ch2[4], zh[0], acc0);
            acc1 = __hfma2(ch2[5], zh[1], acc1);
            acc0 = __hfma2(ch2[6], zh[2], acc0);
            acc1 = __hfma2(ch2[7], zh[3], acc1);
        }
        float2 f0 = __half22float2(acc0);
        float2 f1 = __half22float2(acc1);
        float a = (f0.x + f0.y) + (f1.x + f1.y);

        a += __shfl_xor_sync(0xffffffffu, a, 1);
        a += __shfl_xor_sync(0xffffffffu, a, 2);
        a += __shfl_xor_sync(0xffffffffu, a, 4);

        if (p == 0 && j <= Kk)
            orow[j] = a;          // norms and 1/TEMP all folded into prep

        z0a = ya; z0b = yb;
    }
}

extern "C" void kernel_launch(void* const* d_in, const int* in_sizes, int n_in,
                              void* d_out, int out_size) {
    const float* z  = (const float*)d_in[0];  // [N, C, L]
    const float* c  = (const float*)d_in[1];  // [N, C, L+1]
    const int*   ni = (const int*)d_in[2];    // [N, L, K]
    float* out = (float*)d_out;               // [N*L, K+1]

    dim3 pg(Ll / 32, 2 * Nn);
    prep_k<<<pg, 512>>>(z, c);

    main_k<<<(Nn * Ll) / 8, 256>>>(ni, out);
}